// round 3
// baseline (speedup 1.0000x reference)
#include <cuda_runtime.h>
#include <math.h>

#define BB 2
#define NN 8192
#define CIN 64
#define CC 128
#define KK 16
#define EPSV 1e-5f

// ---------------- device scratch (no allocations allowed) -------------------
__device__ int   g_idx[BB*NN*KK];
__device__ float g_nf [(size_t)BB*NN*CC];
__device__ float g_aq [(size_t)BB*NN*CC];
__device__ float g_ak [(size_t)BB*NN*CC];
__device__ float g_v  [(size_t)BB*NN*CC];
__device__ float g_y5 [(size_t)BB*NN*CC];
__device__ float g_t1 [(size_t)BB*NN*KK*CC];     // 134 MB
__device__ float g_M  [CC*CC];
__device__ float g_Wq2[CC*CC];
__device__ float g_Wk2[CC*CC];
__device__ float g_ccv[CC];
__device__ float g_part1[1024*16];
__device__ float g_part2[8192*16];
__device__ float g_part3[512*16];
__device__ float g_sc1[BB*CC], g_sh1[BB*CC];
__device__ float g_sc2[BB*CC], g_sh2[BB*CC];
__device__ float g_sc3[BB*CC], g_sh3[BB*CC];

// 16-wide FMA step: one weight scalar times 16 positions in smem (pitch 20)
#define GSTEP16(wv, base) { \
  float4 x0=*(const float4*)((base));    float4 x1=*(const float4*)((base)+4); \
  float4 x2=*(const float4*)((base)+8);  float4 x3=*(const float4*)((base)+12); \
  acc[0]=fmaf(wv,x0.x,acc[0]);  acc[1]=fmaf(wv,x0.y,acc[1]); \
  acc[2]=fmaf(wv,x0.z,acc[2]);  acc[3]=fmaf(wv,x0.w,acc[3]); \
  acc[4]=fmaf(wv,x1.x,acc[4]);  acc[5]=fmaf(wv,x1.y,acc[5]); \
  acc[6]=fmaf(wv,x1.z,acc[6]);  acc[7]=fmaf(wv,x1.w,acc[7]); \
  acc[8]=fmaf(wv,x2.x,acc[8]);  acc[9]=fmaf(wv,x2.y,acc[9]); \
  acc[10]=fmaf(wv,x2.z,acc[10]);acc[11]=fmaf(wv,x2.w,acc[11]); \
  acc[12]=fmaf(wv,x3.x,acc[12]);acc[13]=fmaf(wv,x3.y,acc[13]); \
  acc[14]=fmaf(wv,x3.z,acc[14]);acc[15]=fmaf(wv,x3.w,acc[15]); }

extern __shared__ float dsm[];

// ---------------- kNN: warp per query, smem candidate tiles -----------------
__global__ void __launch_bounds__(256) k_knn(const float* __restrict__ xyz) {
  __shared__ float4 sp[1024];
  int b = blockIdx.y;
  int n = blockIdx.x * 8 + (threadIdx.x >> 5);
  int lane = threadIdx.x & 31;
  const float* xb = xyz + (size_t)b * 3 * NN;
  float qx = xb[n], qy = xb[NN + n], qz = xb[2 * NN + n];
  float qsq = __fadd_rn(__fadd_rn(__fmul_rn(qx,qx), __fmul_rn(qy,qy)), __fmul_rn(qz,qz));
  float bd[16]; int bi[16];
  #pragma unroll
  for (int i = 0; i < 16; i++) { bd[i] = 3.4e38f; bi[i] = 0; }
  float worstv = 3.4e38f; int worsts = 0;
  for (int t0 = 0; t0 < NN; t0 += 1024) {
    __syncthreads();
    for (int e = threadIdx.x; e < 1024; e += 256) {
      float x = xb[t0+e], y = xb[NN+t0+e], z = xb[2*NN+t0+e];
      float sq = __fadd_rn(__fadd_rn(__fmul_rn(x,x), __fmul_rn(y,y)), __fmul_rn(z,z));
      sp[e] = make_float4(x, y, z, sq);
    }
    __syncthreads();
    for (int j = lane; j < 1024; j += 32) {
      float4 c = sp[j];
      float inner = __fadd_rn(__fadd_rn(__fmul_rn(qx,c.x), __fmul_rn(qy,c.y)), __fmul_rn(qz,c.z));
      float d2 = __fsub_rn(__fadd_rn(qsq, c.w), __fmul_rn(2.0f, inner));
      if (d2 < worstv) {
        int ci = t0 + j;
        #pragma unroll
        for (int i = 0; i < 16; i++) if (i == worsts) { bd[i] = d2; bi[i] = ci; }
        worstv = bd[0]; worsts = 0;
        #pragma unroll
        for (int i = 1; i < 16; i++) if (bd[i] > worstv) { worstv = bd[i]; worsts = i; }
      }
    }
  }
  unsigned used = 0;
  int* outp = g_idx + ((size_t)b * NN + n) * KK;
  for (int r = 0; r < 16; r++) {
    float mv = 3.4e38f; int mi = -1, ms = 0;
    #pragma unroll
    for (int i = 0; i < 16; i++)
      if (!((used >> i) & 1) && bd[i] < mv) { mv = bd[i]; mi = bi[i]; ms = i; }
    float bv = mv; int bidx = mi; int bl = lane;
    #pragma unroll
    for (int off = 16; off >= 1; off >>= 1) {
      float ov = __shfl_xor_sync(0xffffffffu, bv, off);
      int   oi = __shfl_xor_sync(0xffffffffu, bidx, off);
      int   ol = __shfl_xor_sync(0xffffffffu, bl, off);
      if (ov < bv || (ov == bv && ol < bl)) { bv = ov; bidx = oi; bl = ol; }
    }
    if (lane == bl) used |= 1u << ms;
    if (lane == 0) outp[r] = bidx;
  }
}

// ---------------- pre conv: feat (B,64,N) -> nf (B,N,128) position-major ----
__global__ void __launch_bounds__(256) k_pre(const float* __restrict__ feat,
                                             const float* __restrict__ W,
                                             const float* __restrict__ bias) {
  __shared__ float wr[CC*65];
  __shared__ float buf[2*CIN*20];
  int tid = threadIdx.x, grp = tid >> 7, co = tid & 127;
  for (int e = tid; e < CC*CIN; e += 256) wr[(e>>6)*65 + (e&63)] = W[e];
  int b = blockIdx.y;
  int n0 = blockIdx.x*32 + grp*16;
  const float* fb = feat + (size_t)b * CIN * NN;
  for (int e = tid; e < 2*CIN*16; e += 256) {
    int g2 = e >> 10, ci = (e >> 4) & 63, p = e & 15;
    buf[g2*(CIN*20) + ci*20 + p] = fb[(size_t)ci*NN + blockIdx.x*32 + g2*16 + p];
  }
  __syncthreads();
  float* gb = buf + grp*(CIN*20);
  float acc[16]; float bv = bias[co];
  #pragma unroll
  for (int p = 0; p < 16; p++) acc[p] = bv;
  #pragma unroll 4
  for (int ci = 0; ci < CIN; ci++) { float w = wr[co*65+ci]; GSTEP16(w, gb + ci*20); }
  float* yb = g_nf + ((size_t)b*NN + n0) * CC;
  #pragma unroll
  for (int p = 0; p < 16; p++) yb[(size_t)p*CC + co] = acc[p];
}

// ---------------- weight folding ------------------------------------------
__global__ void k_combine(const float* __restrict__ A1, const float* __restrict__ Wq,
                          const float* __restrict__ Wk, const float* __restrict__ W2,
                          const float* __restrict__ a1b, const float* __restrict__ qb,
                          const float* __restrict__ kb, const float* __restrict__ p2b) {
  int z = blockIdx.x;
  if (z < 3) {
    const float* X = (z==0) ? Wq : ((z==1) ? Wk : W2);
    float* O = (z==0) ? g_Wq2 : ((z==1) ? g_Wk2 : g_M);
    for (int e = threadIdx.x; e < CC*CC; e += 256) {
      int o = e >> 7, c = e & 127;
      float s0=0.f, s1=0.f;
      for (int j = 0; j < CC; j += 2) {
        s0 = fmaf(A1[o*CC+j],   X[j*CC+c],     s0);
        s1 = fmaf(A1[o*CC+j+1], X[(j+1)*CC+c], s1);
      }
      O[e] = s0 + s1;
    }
  } else {
    for (int c = threadIdx.x; c < CC; c += 256) {
      float s = a1b[c];
      for (int j = 0; j < CC; j++) s = fmaf(A1[c*CC+j], qb[j]-kb[j]+p2b[j], s);
      g_ccv[c] = s;
    }
  }
}

// ---------------- GN1 stats over y1 = pos1_w@rel + pos1_b ------------------
__global__ void __launch_bounds__(256) k_gn1(const float* __restrict__ xyz,
                                             const float* __restrict__ p1w,
                                             const float* __restrict__ p1b) {
  __shared__ float sw[CC*4];
  __shared__ float sacc[16];
  int tid = threadIdx.x;
  for (int e = tid; e < CC*3; e += 256) sw[e] = p1w[e];
  for (int e = tid; e < CC; e += 256) sw[CC*3+e] = p1b[e];
  if (tid < 16) sacc[tid] = 0.f;
  __syncthreads();
  size_t r = (size_t)blockIdx.x*256 + tid;       // (b,n,k) row
  int b = (int)(r >> 17);
  int n = (int)((r >> 4) & 8191);
  int j = g_idx[r];
  const float* xb = xyz + (size_t)b*3*NN;
  float rx = xb[j]-xb[n], ry = xb[NN+j]-xb[NN+n], rz = xb[2*NN+j]-xb[2*NN+n];
  #pragma unroll
  for (int g = 0; g < 8; g++) {
    float s = 0.f, ss = 0.f;
    #pragma unroll
    for (int cc = 0; cc < 16; cc++) {
      int c = g*16 + cc;
      float y = fmaf(sw[c*3], rx, fmaf(sw[c*3+1], ry, fmaf(sw[c*3+2], rz, sw[CC*3+c])));
      s += y; ss = fmaf(y, y, ss);
    }
    atomicAdd(&sacc[g], s); atomicAdd(&sacc[8+g], ss);
  }
  __syncthreads();
  if (tid < 16) g_part1[blockIdx.x*16 + tid] = sacc[tid];
}

// ---------------- stats reduce -> per-(b,c) scale/shift --------------------
__global__ void k_reduce(int which, int nblkb, float invcnt,
                         const float* __restrict__ gamma, const float* __restrict__ beta) {
  const float* P = (which==0) ? g_part1 : ((which==1) ? g_part2 : g_part3);
  float* sc = (which==0) ? g_sc1 : ((which==1) ? g_sc2 : g_sc3);
  float* sh = (which==0) ? g_sh1 : ((which==1) ? g_sh2 : g_sh3);
  int b = blockIdx.x, tid = threadIdx.x;
  int s = tid & 15, grp = tid >> 4;
  double acc = 0.0;
  for (int blk = grp; blk < nblkb; blk += 16)
    acc += (double)P[((size_t)b*nblkb + blk)*16 + s];
  __shared__ double rr[16][17];
  __shared__ double fin[16];
  rr[grp][s] = acc;
  __syncthreads();
  if (tid < 16) { double t = 0.0; for (int i = 0; i < 16; i++) t += rr[i][tid]; fin[tid] = t; }
  __syncthreads();
  if (tid < CC) {
    int g8 = tid >> 4;
    double mean = fin[g8] * (double)invcnt;
    double var  = fin[8+g8] * (double)invcnt - mean*mean;
    float rstd = rsqrtf((float)var + EPSV);
    float scv = gamma[tid] * rstd;
    sc[b*CC+tid] = scv;
    sh[b*CC+tid] = beta[tid] - (float)mean * scv;
  }
}

// ---------------- generic position-major 128x128 conv ----------------------
__global__ void __launch_bounds__(256) k_conv_pm(const float* __restrict__ X,
                                                 const float* __restrict__ W,
                                                 const float* __restrict__ bias,
                                                 float* __restrict__ Y,
                                                 float* __restrict__ partials) {
  float* wr = dsm;                       // 128 x pitch129
  float* gb = dsm + CC*129;              // 2 x 128 x 20
  float* sacc = gb + 2*CC*20;            // 16
  int tid = threadIdx.x, grp = tid >> 7, co = tid & 127;
  for (int e = tid; e < CC*CC; e += 256) wr[(e>>7)*129 + (e&127)] = W[e];
  if (tid < 16) sacc[tid] = 0.f;
  size_t r0 = (size_t)blockIdx.x*32 + grp*16;
  float* g = gb + grp*(CC*20);
  #pragma unroll
  for (int p = 0; p < 16; p++) g[co*20+p] = X[(r0+p)*CC + co];
  __syncthreads();
  float acc[16]; float bv = bias[co];
  #pragma unroll
  for (int p = 0; p < 16; p++) acc[p] = bv;
  #pragma unroll 4
  for (int ci = 0; ci < CC; ci++) { float w = wr[co*129+ci]; GSTEP16(w, g + ci*20); }
  float s = 0.f, ss = 0.f;
  #pragma unroll
  for (int p = 0; p < 16; p++) { Y[(r0+p)*CC + co] = acc[p]; s += acc[p]; ss = fmaf(acc[p],acc[p],ss); }
  if (partials) {
    atomicAdd(&sacc[co>>4], s); atomicAdd(&sacc[8+(co>>4)], ss);
    __syncthreads();
    if (tid < 16) partials[blockIdx.x*16 + tid] = sacc[tid];
  }
}

// ---------------- fused att1: t1 = M@p1 + Aq - Ak_g + cvec, + GN2 stats ----
__global__ void __launch_bounds__(256) k_att1(const float* __restrict__ xyz,
                                              const float* __restrict__ p1w,
                                              const float* __restrict__ p1b) {
  float* wr = dsm;
  float* gb = dsm + CC*129;
  float* sacc = gb + 2*CC*20;            // 16
  float* rel = sacc + 16;                // 2 x 16 x 4
  int*   jsh = (int*)(rel + 2*64);       // 2 x 16
  int tid = threadIdx.x, grp = tid >> 7, co = tid & 127;
  for (int e = tid; e < CC*CC; e += 256) wr[(e>>7)*129 + (e&127)] = g_M[e];
  if (tid < 16) sacc[tid] = 0.f;
  int pg = blockIdx.x*2 + grp;
  int b = pg >> 13, n = pg & 8191;
  const float* xb = xyz + (size_t)b*3*NN;
  if (co < 16) {
    int j = g_idx[(size_t)pg*KK + co];
    jsh[grp*16+co] = j;
    float* rr = rel + grp*64 + co*4;
    rr[0] = xb[j]-xb[n]; rr[1] = xb[NN+j]-xb[NN+n]; rr[2] = xb[2*NN+j]-xb[2*NN+n];
  }
  __syncthreads();
  float w0 = p1w[co*3], w1 = p1w[co*3+1], w2 = p1w[co*3+2], pb = p1b[co];
  float s1 = g_sc1[b*CC+co], h1 = g_sh1[b*CC+co];
  float* g = gb + grp*(CC*20);
  #pragma unroll
  for (int k = 0; k < 16; k++) {
    float* rr = rel + grp*64 + k*4;
    float y = fmaf(w0, rr[0], fmaf(w1, rr[1], fmaf(w2, rr[2], pb)));
    y = s1*y + h1;
    g[co*20+k] = (y >= 0.f) ? y : 0.1f*y;
  }
  __syncthreads();
  float base = g_ccv[co] + g_aq[(size_t)pg*CC + co];
  float acc[16];
  #pragma unroll
  for (int k = 0; k < 16; k++) acc[k] = base;
  #pragma unroll 4
  for (int ci = 0; ci < CC; ci++) { float w = wr[co*129+ci]; GSTEP16(w, g + ci*20); }
  float s = 0.f, ss = 0.f;
  float* outp = g_t1 + (size_t)pg*KK*CC;
  #pragma unroll
  for (int k = 0; k < 16; k++) {
    int j = jsh[grp*16+k];
    float v = acc[k] - g_ak[((size_t)b*NN + j)*CC + co];
    outp[(size_t)k*CC + co] = v;
    s += v; ss = fmaf(v, v, ss);
  }
  atomicAdd(&sacc[co>>4], s); atomicAdd(&sacc[8+(co>>4)], ss);
  __syncthreads();
  if (tid < 16) g_part2[blockIdx.x*16 + tid] = sacc[tid];
}

// ---------------- fused att2 + softmax + V-agg + residual ------------------
__global__ void __launch_bounds__(256) k_att2(const float* __restrict__ W,
                                              const float* __restrict__ bias) {
  float* wr = dsm;
  float* gb = dsm + CC*129;
  float* sacc = gb + 2*CC*20;
  float* rel = sacc + 16;
  int*   jsh = (int*)(rel + 2*64);
  int tid = threadIdx.x, grp = tid >> 7, co = tid & 127;
  for (int e = tid; e < CC*CC; e += 256) wr[(e>>7)*129 + (e&127)] = W[e];
  int pg = blockIdx.x*2 + grp;
  int b = pg >> 13;
  if (co < 16) jsh[grp*16+co] = g_idx[(size_t)pg*KK + co];
  float s2 = g_sc2[b*CC+co], h2 = g_sh2[b*CC+co];
  const float* tp = g_t1 + (size_t)pg*KK*CC;
  float* g = gb + grp*(CC*20);
  #pragma unroll
  for (int k = 0; k < 16; k++) {
    float y = fmaf(s2, tp[(size_t)k*CC + co], h2);
    g[co*20+k] = (y >= 0.f) ? y : 0.1f*y;
  }
  __syncthreads();
  float acc[16]; float bv = bias[co];
  #pragma unroll
  for (int k = 0; k < 16; k++) acc[k] = bv;
  #pragma unroll 4
  for (int ci = 0; ci < CC; ci++) { float w = wr[co*129+ci]; GSTEP16(w, g + ci*20); }
  float m = acc[0];
  #pragma unroll
  for (int k = 1; k < 16; k++) m = fmaxf(m, acc[k]);
  float sum = 0.f;
  #pragma unroll
  for (int k = 0; k < 16; k++) { acc[k] = __expf(acc[k]-m); sum += acc[k]; }
  float inv = 1.f / sum;
  float o = 0.f;
  #pragma unroll
  for (int k = 0; k < 16; k++) {
    int j = jsh[grp*16+k];
    o = fmaf(acc[k]*inv, g_v[((size_t)b*NN + j)*CC + co], o);
  }
  g_y5[(size_t)pg*CC + co] = o + g_nf[(size_t)pg*CC + co];
}

// ---------------- final GN3 + lrelu + transpose to (B,C,N) -----------------
__global__ void k_final(float* __restrict__ out) {
  __shared__ float t[32][33];
  int b = blockIdx.z, c0 = blockIdx.y*32, n0 = blockIdx.x*32;
  int tx = threadIdx.x, ty = threadIdx.y;
  float scv = g_sc3[b*CC + c0 + tx], shv = g_sh3[b*CC + c0 + tx];
  #pragma unroll
  for (int i = 0; i < 4; i++) {
    int n = n0 + ty*4 + i;
    float x = g_aq[((size_t)b*NN + n)*CC + c0 + tx];
    float y = fmaf(scv, x, shv);
    t[tx][ty*4+i] = (y >= 0.f) ? y : 0.1f*y;
  }
  __syncthreads();
  #pragma unroll
  for (int i = 0; i < 4; i++) {
    int c = c0 + ty*4 + i;
    out[((size_t)b*CC + c)*NN + n0 + tx] = t[ty*4+i][tx];
  }
}

// ---------------- launch ----------------------------------------------------
extern "C" void kernel_launch(void* const* d_in, const int* in_sizes, int n_in,
                              void* d_out, int out_size) {
  const float* xyz    = (const float*)d_in[0];
  const float* feat   = (const float*)d_in[1];
  const float* pre_w  = (const float*)d_in[2];
  const float* pre_b  = (const float*)d_in[3];
  const float* wq_w   = (const float*)d_in[4];
  const float* wq_b   = (const float*)d_in[5];
  const float* wk_w   = (const float*)d_in[6];
  const float* wk_b   = (const float*)d_in[7];
  const float* wv_w   = (const float*)d_in[8];
  const float* wv_b   = (const float*)d_in[9];
  const float* pos1_w = (const float*)d_in[10];
  const float* pos1_b = (const float*)d_in[11];
  const float* pos1_g = (const float*)d_in[12];
  const float* pos1_be= (const float*)d_in[13];
  // pos2_w d_in[14], pos2_b d_in[15] consumed via folding
  const float* att1_w = (const float*)d_in[16];
  const float* att1_b = (const float*)d_in[17];
  const float* att1_g = (const float*)d_in[18];
  const float* att1_be= (const float*)d_in[19];
  const float* att2_w = (const float*)d_in[20];
  const float* att2_b = (const float*)d_in[21];
  const float* post_w = (const float*)d_in[22];
  const float* post_b = (const float*)d_in[23];
  const float* post_g = (const float*)d_in[24];
  const float* post_be= (const float*)d_in[25];
  float* out = (float*)d_out;

  const int SMEMB = (CC*129 + 2*CC*20 + 16 + 2*64 + 32 + 16) * 4;
  cudaFuncSetAttribute(k_conv_pm, cudaFuncAttributeMaxDynamicSharedMemorySize, SMEMB);
  cudaFuncSetAttribute(k_att1,    cudaFuncAttributeMaxDynamicSharedMemorySize, SMEMB);
  cudaFuncSetAttribute(k_att2,    cudaFuncAttributeMaxDynamicSharedMemorySize, SMEMB);

  void *p_nf, *p_aq, *p_ak, *p_v, *p_y5, *p_Wq2, *p_Wk2, *p_part3;
  cudaGetSymbolAddress(&p_nf,  g_nf);
  cudaGetSymbolAddress(&p_aq,  g_aq);
  cudaGetSymbolAddress(&p_ak,  g_ak);
  cudaGetSymbolAddress(&p_v,   g_v);
  cudaGetSymbolAddress(&p_y5,  g_y5);
  cudaGetSymbolAddress(&p_Wq2, g_Wq2);
  cudaGetSymbolAddress(&p_Wk2, g_Wk2);
  cudaGetSymbolAddress(&p_part3, g_part3);

  k_knn<<<dim3(NN/8, BB), 256>>>(xyz);
  k_pre<<<dim3(NN/32, BB), 256>>>(feat, pre_w, pre_b);
  k_combine<<<4, 256>>>(att1_w, wq_w, wk_w, (const float*)d_in[14],
                        att1_b, wq_b, wk_b, (const float*)d_in[15]);
  k_gn1<<<1024, 256>>>(xyz, pos1_w, pos1_b);
  k_reduce<<<2, 256>>>(0, 512, 1.f/2097152.f, pos1_g, pos1_be);
  k_conv_pm<<<512, 256, SMEMB>>>((const float*)p_nf, (const float*)p_Wq2, att1_b, (float*)p_aq, nullptr);
  k_conv_pm<<<512, 256, SMEMB>>>((const float*)p_nf, (const float*)p_Wk2, att1_b, (float*)p_ak, nullptr);
  k_conv_pm<<<512, 256, SMEMB>>>((const float*)p_nf, wv_w, wv_b, (float*)p_v, nullptr);
  k_att1<<<BB*NN/2, 256, SMEMB>>>(xyz, pos1_w, pos1_b);
  k_reduce<<<2, 256>>>(1, 4096, 1.f/2097152.f, att1_g, att1_be);
  k_att2<<<BB*NN/2, 256, SMEMB>>>(att2_w, att2_b);
  k_conv_pm<<<512, 256, SMEMB>>>((const float*)p_y5, post_w, post_b, (float*)p_aq, (float*)p_part3);
  k_reduce<<<2, 256>>>(2, 256, 1.f/131072.f, post_g, post_be);
  k_final<<<dim3(NN/32, CC/32, BB), dim3(32, 8)>>>(out);
}